// round 1
// baseline (speedup 1.0000x reference)
#include <cuda_runtime.h>
#include <cstdint>
#include <cstddef>

#define T_STEPS 2048
#define N_ENV   256
#define HID     128
#define G3      384          // 3*HID
#define IDIM    128
#define M_TOTAL (T_STEPS*N_ENV)   // 524288
#define LDA     132          // padded smem row (floats)

// Scratch for gi = x @ w_ih^T + b_ih : [M_TOTAL, G3] fp32 (805 MB)
__device__ float g_gi[(size_t)M_TOTAL * G3];

// ---------------------------------------------------------------------------
// helpers
// ---------------------------------------------------------------------------
__device__ __forceinline__ unsigned f2tf(float f){
  unsigned u; asm("cvt.rna.tf32.f32 %0, %1;" : "=r"(u) : "f"(f)); return u;
}
__device__ __forceinline__ void mma8(float* c, const unsigned* a, const unsigned* b){
  asm volatile("mma.sync.aligned.m16n8k8.row.col.f32.tf32.tf32.f32 "
      "{%0,%1,%2,%3}, {%4,%5,%6,%7}, {%8,%9}, {%0,%1,%2,%3};"
      : "+f"(c[0]), "+f"(c[1]), "+f"(c[2]), "+f"(c[3])
      : "r"(a[0]), "r"(a[1]), "r"(a[2]), "r"(a[3]), "r"(b[0]), "r"(b[1]));
}
__device__ __forceinline__ void cp16(float* dst, const float* src){
  unsigned s = (unsigned)__cvta_generic_to_shared(dst);
  asm volatile("cp.async.cg.shared.global [%0], [%1], 16;" :: "r"(s), "l"(src));
}
__device__ __forceinline__ unsigned long long pk2(float lo, float hi){
  unsigned long long r; asm("mov.b64 %0, {%1,%2};" : "=l"(r) : "f"(lo), "f"(hi)); return r;
}
__device__ __forceinline__ void fma2(unsigned long long& d, unsigned long long a, unsigned long long b){
  asm("fma.rn.f32x2 %0, %1, %2, %0;" : "+l"(d) : "l"(a), "l"(b));
}
__device__ __forceinline__ float2 upk(unsigned long long v){
  float lo, hi; asm("mov.b64 {%0,%1}, %2;" : "=f"(lo), "=f"(hi) : "l"(v));
  return make_float2(lo, hi);
}
__device__ __forceinline__ float sigf(float x){
  return __fdividef(1.0f, 1.0f + __expf(-x));
}
__device__ __forceinline__ float tanhf_(float x){
  return __fdividef(2.0f, 1.0f + __expf(-2.0f*x)) - 1.0f;
}

// ---------------------------------------------------------------------------
// K1: gi = x @ w_ih^T + b_ih   (tf32 mma.sync, B resident in smem, A streamed)
// grid (3, 128), block 256. CTA (nb, slab): n-block nb, m-tiles slab + 128*it.
// ---------------------------------------------------------------------------
__global__ void __launch_bounds__(256) k1_gi(const float* __restrict__ x,
                                             const float* __restrict__ w_ih,
                                             const float* __restrict__ b_ih){
  extern __shared__ float sm[];
  float* Bs   = sm;                    // [128][LDA]
  float* As   = sm + 128*LDA;          // [2][128][LDA]
  float* bias = sm + 3*128*LDA;        // [128]

  const int tid  = threadIdx.x;
  const int nb   = blockIdx.x;         // 0..2
  const int slab = blockIdx.y;         // 0..127
  const int gbase = nb * 128;

  // Load B block (w_ih rows gbase..gbase+127) with tf32 rounding
  for (int idx = tid; idx < 128*32; idx += 256){
    int r = idx >> 5, c4 = idx & 31;
    float4 v = reinterpret_cast<const float4*>(w_ih + (size_t)(gbase + r)*IDIM)[c4];
    float* d = Bs + r*LDA + c4*4;
    d[0] = __uint_as_float(f2tf(v.x));
    d[1] = __uint_as_float(f2tf(v.y));
    d[2] = __uint_as_float(f2tf(v.z));
    d[3] = __uint_as_float(f2tf(v.w));
  }
  if (tid < 128) bias[tid] = b_ih[gbase + tid];

  const int lane = tid & 31, wid = tid >> 5;
  const int wm = wid >> 1, wn = wid & 1;
  const int grp = lane >> 2, qid = lane & 3;

  // prefetch A tile 0 into buf 0
  {
    const float* srcb = x + (size_t)slab * 128 * IDIM;
    #pragma unroll
    for (int i = 0; i < 16; i++){
      int c = tid + 256*i;
      int r = c >> 5, c16 = c & 31;
      cp16(As + r*LDA + c16*4, srcb + (size_t)r*IDIM + c16*4);
    }
    asm volatile("cp.async.commit_group;");
  }

  for (int it = 0; it < 32; it++){
    const int buf = it & 1;
    if (it + 1 < 32){
      int mt = slab + (it+1)*128;
      const float* srcb = x + (size_t)mt * 128 * IDIM;
      float* dstb = As + ((it+1)&1)*128*LDA;
      #pragma unroll
      for (int i = 0; i < 16; i++){
        int c = tid + 256*i;
        int r = c >> 5, c16 = c & 31;
        cp16(dstb + r*LDA + c16*4, srcb + (size_t)r*IDIM + c16*4);
      }
      asm volatile("cp.async.commit_group;");
      asm volatile("cp.async.wait_group 1;");
    } else {
      asm volatile("cp.async.wait_group 0;");
    }
    __syncthreads();

    float c[2][8][4];
    #pragma unroll
    for (int am=0;am<2;am++)
      #pragma unroll
      for(int an=0;an<8;an++)
        #pragma unroll
        for(int k=0;k<4;k++) c[am][an][k]=0.f;

    const float* A = As + buf*128*LDA;
    for (int k0 = 0; k0 < 128; k0 += 8){
      unsigned af[2][4];
      #pragma unroll
      for (int am=0; am<2; am++){
        int r0 = wm*32 + am*16 + grp;
        af[am][0] = f2tf(A[r0*LDA + k0 + qid]);
        af[am][1] = f2tf(A[(r0+8)*LDA + k0 + qid]);
        af[am][2] = f2tf(A[r0*LDA + k0 + qid + 4]);
        af[am][3] = f2tf(A[(r0+8)*LDA + k0 + qid + 4]);
      }
      unsigned bf[8][2];
      #pragma unroll
      for (int an=0; an<8; an++){
        int nr = wn*64 + an*8 + grp;
        bf[an][0] = __float_as_uint(Bs[nr*LDA + k0 + qid]);
        bf[an][1] = __float_as_uint(Bs[nr*LDA + k0 + qid + 4]);
      }
      #pragma unroll
      for (int am=0; am<2; am++)
        #pragma unroll
        for (int an=0; an<8; an++)
          mma8(c[am][an], af[am], bf[an]);
    }
    __syncthreads();  // compute done before next prefetch overwrites buf

    // epilogue: add bias, store fp32
    const int mrow = (slab + it*128) * 128;
    #pragma unroll
    for (int am=0; am<2; am++){
      int r0 = mrow + wm*32 + am*16 + grp;
      #pragma unroll
      for (int an=0; an<8; an++){
        int colL = wn*64 + an*8 + 2*qid;
        float b0 = bias[colL], b1 = bias[colL+1];
        float2 v0 = make_float2(c[am][an][0]+b0, c[am][an][1]+b1);
        float2 v1 = make_float2(c[am][an][2]+b0, c[am][an][3]+b1);
        *reinterpret_cast<float2*>(&g_gi[(size_t)r0*G3 + gbase + colL]) = v0;
        *reinterpret_cast<float2*>(&g_gi[(size_t)(r0+8)*G3 + gbase + colL]) = v1;
      }
    }
  }
}

// ---------------------------------------------------------------------------
// K2: persistent GRU scan. 128 CTAs x 2 envs x 384 threads.
// Thread g holds w_hh row g in registers (64x f32x2). h in smem, broadcast.
// ---------------------------------------------------------------------------
__global__ void __launch_bounds__(384, 1) k2_scan(
    const float* __restrict__ h0,
    const float* __restrict__ masks,
    const float* __restrict__ w_hh,
    const float* __restrict__ b_hh,
    float* __restrict__ outs,
    float* __restrict__ h_final)
{
  __shared__ __align__(16) float h_s[2][HID];
  __shared__ float gh_s[2][G3];
  __shared__ float gi_s[2][G3];
  __shared__ float m_s[2][2];

  const int g  = threadIdx.x;          // 0..383 == gate row
  const int e0 = blockIdx.x * 2;       // first env of this CTA

  // Load this thread's w_hh row into registers as packed f32x2 pairs
  unsigned long long wq[64];
  {
    const float4* wr = reinterpret_cast<const float4*>(w_hh + (size_t)g * HID);
    #pragma unroll
    for (int i = 0; i < 32; i++){
      float4 v = wr[i];
      wq[2*i]   = pk2(v.x, v.y);
      wq[2*i+1] = pk2(v.z, v.w);
    }
  }
  const float bh = b_hh[g];

  if (g < 256) h_s[g>>7][g&127] = h0[(size_t)(e0 + (g>>7))*HID + (g&127)];
  if (g < 2)   m_s[0][g] = masks[e0 + g];

  const size_t off0 = (size_t)e0*G3 + g;
  float gi0 = g_gi[off0];
  float gi1 = g_gi[off0 + G3];
  __syncthreads();

  for (int t = 0; t < T_STEPS; t++){
    const int par = t & 1;
    const float m0 = m_s[par][0];
    const float m1 = m_s[par][1];

    // stage current gi for the gate phase, prefetch next step's gi/mask
    gi_s[0][g] = gi0;
    gi_s[1][g] = gi1;
    if (t + 1 < T_STEPS){
      const float* p = g_gi + (size_t)(t+1)*(N_ENV*G3) + off0;
      gi0 = p[0];
      gi1 = p[G3];
      if (g < 2) m_s[(t+1)&1][g] = masks[(size_t)(t+1)*N_ENV + e0 + g];
    }

    // matvec: gh_lin = W_hh . h  (packed f32x2 FMA, weights in regs)
    unsigned long long a0=0, b0=0, a1=0, b1=0;
    const ulonglong2* h0p = reinterpret_cast<const ulonglong2*>(h_s[0]);
    const ulonglong2* h1p = reinterpret_cast<const ulonglong2*>(h_s[1]);
    #pragma unroll
    for (int i = 0; i < 32; i++){
      ulonglong2 v0 = h0p[i];
      fma2(a0, wq[2*i],   v0.x);
      fma2(b0, wq[2*i+1], v0.y);
      ulonglong2 v1 = h1p[i];
      fma2(a1, wq[2*i],   v1.x);
      fma2(b1, wq[2*i+1], v1.y);
    }
    float2 s0a = upk(a0), s0b = upk(b0), s1a = upk(a1), s1b = upk(b1);
    float sum0 = (s0a.x + s0b.x) + (s0a.y + s0b.y);
    float sum1 = (s1a.x + s1b.x) + (s1a.y + s1b.y);
    // mask commutes with the linear map: W(h*m) = m*(W h)
    gh_s[0][g] = fmaf(m0, sum0, bh);
    gh_s[1][g] = fmaf(m1, sum1, bh);
    __syncthreads();

    if (g < 256){
      const int e = g >> 7, j = g & 127;
      const float me = e ? m1 : m0;
      float r = sigf(gi_s[e][j]       + gh_s[e][j]);
      float z = sigf(gi_s[e][128 + j] + gh_s[e][128 + j]);
      float n = tanhf_(fmaf(r, gh_s[e][256 + j], gi_s[e][256 + j]));
      float hm = me * h_s[e][j];
      float hn = fmaf(z, hm - n, n);    // (1-z)*n + z*hm
      h_s[e][j] = hn;
      outs[((size_t)t*N_ENV + e0 + e)*HID + j] = hn;
      if (h_final != nullptr && t == T_STEPS-1)
        h_final[(size_t)(e0+e)*HID + j] = hn;
    }
    __syncthreads();
  }
}

// ---------------------------------------------------------------------------
extern "C" void kernel_launch(void* const* d_in, const int* in_sizes, int n_in,
                              void* d_out, int out_size){
  (void)in_sizes; (void)n_in;
  const float* x     = (const float*)d_in[0];
  const float* h0    = (const float*)d_in[1];
  const float* masks = (const float*)d_in[2];
  const float* w_ih  = (const float*)d_in[3];
  const float* w_hh  = (const float*)d_in[4];
  const float* b_ih  = (const float*)d_in[5];
  const float* b_hh  = (const float*)d_in[6];

  float* outs = (float*)d_out;
  float* hf = nullptr;
  if ((long long)out_size >= (long long)M_TOTAL*HID + (long long)N_ENV*HID)
    hf = outs + (size_t)M_TOTAL*HID;

  const int k1_smem = (3*128*LDA + 128) * (int)sizeof(float);
  cudaFuncSetAttribute(k1_gi, cudaFuncAttributeMaxDynamicSharedMemorySize, k1_smem);
  k1_gi<<<dim3(3,128), 256, k1_smem>>>(x, w_ih, b_ih);
  k2_scan<<<128, 384>>>(h0, masks, w_hh, b_hh, outs, hf);
}

// round 2
// speedup vs baseline: 1.1402x; 1.1402x over previous
#include <cuda_runtime.h>
#include <cstdint>
#include <cstddef>

#define T_STEPS 2048
#define N_ENV   256
#define HID     128
#define G3      384          // 3*HID
#define IDIM    128
#define M_TOTAL (T_STEPS*N_ENV)   // 524288
#define LDA     132          // padded smem row (floats)

// Scratch for gi = x @ w_ih^T + b_ih : [M_TOTAL, G3] fp32 (805 MB)
__device__ float g_gi[(size_t)M_TOTAL * G3];

// ---------------------------------------------------------------------------
// helpers
// ---------------------------------------------------------------------------
__device__ __forceinline__ unsigned f2tf(float f){
  unsigned u; asm("cvt.rna.tf32.f32 %0, %1;" : "=r"(u) : "f"(f)); return u;
}
__device__ __forceinline__ void mma8(float* c, const unsigned* a, const unsigned* b){
  asm volatile("mma.sync.aligned.m16n8k8.row.col.f32.tf32.tf32.f32 "
      "{%0,%1,%2,%3}, {%4,%5,%6,%7}, {%8,%9}, {%0,%1,%2,%3};"
      : "+f"(c[0]), "+f"(c[1]), "+f"(c[2]), "+f"(c[3])
      : "r"(a[0]), "r"(a[1]), "r"(a[2]), "r"(a[3]), "r"(b[0]), "r"(b[1]));
}
__device__ __forceinline__ void cp16(float* dst, const float* src){
  unsigned s = (unsigned)__cvta_generic_to_shared(dst);
  asm volatile("cp.async.cg.shared.global [%0], [%1], 16;" :: "r"(s), "l"(src));
}
__device__ __forceinline__ unsigned long long pk2(float lo, float hi){
  unsigned long long r; asm("mov.b64 %0, {%1,%2};" : "=l"(r) : "f"(lo), "f"(hi)); return r;
}
__device__ __forceinline__ void fma2(unsigned long long& d, unsigned long long a, unsigned long long b){
  asm("fma.rn.f32x2 %0, %1, %2, %0;" : "+l"(d) : "l"(a), "l"(b));
}
__device__ __forceinline__ float2 upk(unsigned long long v){
  float lo, hi; asm("mov.b64 {%0,%1}, %2;" : "=f"(lo), "=f"(hi) : "l"(v));
  return make_float2(lo, hi);
}
__device__ __forceinline__ float sigf(float x){
  return __fdividef(1.0f, 1.0f + __expf(-x));
}
__device__ __forceinline__ float tanhf_(float x){
  return __fdividef(2.0f, 1.0f + __expf(-2.0f*x)) - 1.0f;
}

// ---------------------------------------------------------------------------
// K1: gi = x @ w_ih^T + b_ih   (tf32 mma.sync, B resident in smem, A streamed)
// ---------------------------------------------------------------------------
__global__ void __launch_bounds__(256) k1_gi(const float* __restrict__ x,
                                             const float* __restrict__ w_ih,
                                             const float* __restrict__ b_ih){
  extern __shared__ float sm[];
  float* Bs   = sm;                    // [128][LDA]
  float* As   = sm + 128*LDA;          // [2][128][LDA]
  float* bias = sm + 3*128*LDA;        // [128]

  const int tid  = threadIdx.x;
  const int nb   = blockIdx.x;         // 0..2
  const int slab = blockIdx.y;         // 0..127
  const int gbase = nb * 128;

  for (int idx = tid; idx < 128*32; idx += 256){
    int r = idx >> 5, c4 = idx & 31;
    float4 v = reinterpret_cast<const float4*>(w_ih + (size_t)(gbase + r)*IDIM)[c4];
    float* d = Bs + r*LDA + c4*4;
    d[0] = __uint_as_float(f2tf(v.x));
    d[1] = __uint_as_float(f2tf(v.y));
    d[2] = __uint_as_float(f2tf(v.z));
    d[3] = __uint_as_float(f2tf(v.w));
  }
  if (tid < 128) bias[tid] = b_ih[gbase + tid];

  const int lane = tid & 31, wid = tid >> 5;
  const int wm = wid >> 1, wn = wid & 1;
  const int grp = lane >> 2, qid = lane & 3;

  {
    const float* srcb = x + (size_t)slab * 128 * IDIM;
    #pragma unroll
    for (int i = 0; i < 16; i++){
      int c = tid + 256*i;
      int r = c >> 5, c16 = c & 31;
      cp16(As + r*LDA + c16*4, srcb + (size_t)r*IDIM + c16*4);
    }
    asm volatile("cp.async.commit_group;");
  }

  for (int it = 0; it < 32; it++){
    const int buf = it & 1;
    if (it + 1 < 32){
      int mt = slab + (it+1)*128;
      const float* srcb = x + (size_t)mt * 128 * IDIM;
      float* dstb = As + ((it+1)&1)*128*LDA;
      #pragma unroll
      for (int i = 0; i < 16; i++){
        int c = tid + 256*i;
        int r = c >> 5, c16 = c & 31;
        cp16(dstb + r*LDA + c16*4, srcb + (size_t)r*IDIM + c16*4);
      }
      asm volatile("cp.async.commit_group;");
      asm volatile("cp.async.wait_group 1;");
    } else {
      asm volatile("cp.async.wait_group 0;");
    }
    __syncthreads();

    float c[2][8][4];
    #pragma unroll
    for (int am=0;am<2;am++)
      #pragma unroll
      for(int an=0;an<8;an++)
        #pragma unroll
        for(int k=0;k<4;k++) c[am][an][k]=0.f;

    const float* A = As + buf*128*LDA;
    for (int k0 = 0; k0 < 128; k0 += 8){
      unsigned af[2][4];
      #pragma unroll
      for (int am=0; am<2; am++){
        int r0 = wm*32 + am*16 + grp;
        af[am][0] = f2tf(A[r0*LDA + k0 + qid]);
        af[am][1] = f2tf(A[(r0+8)*LDA + k0 + qid]);
        af[am][2] = f2tf(A[r0*LDA + k0 + qid + 4]);
        af[am][3] = f2tf(A[(r0+8)*LDA + k0 + qid + 4]);
      }
      unsigned bf[8][2];
      #pragma unroll
      for (int an=0; an<8; an++){
        int nr = wn*64 + an*8 + grp;
        bf[an][0] = __float_as_uint(Bs[nr*LDA + k0 + qid]);
        bf[an][1] = __float_as_uint(Bs[nr*LDA + k0 + qid + 4]);
      }
      #pragma unroll
      for (int am=0; am<2; am++)
        #pragma unroll
        for (int an=0; an<8; an++)
          mma8(c[am][an], af[am], bf[an]);
    }
    __syncthreads();

    const int mrow = (slab + it*128) * 128;
    #pragma unroll
    for (int am=0; am<2; am++){
      int r0 = mrow + wm*32 + am*16 + grp;
      #pragma unroll
      for (int an=0; an<8; an++){
        int colL = wn*64 + an*8 + 2*qid;
        float b0 = bias[colL], b1 = bias[colL+1];
        float2 v0 = make_float2(c[am][an][0]+b0, c[am][an][1]+b1);
        float2 v1 = make_float2(c[am][an][2]+b0, c[am][an][3]+b1);
        *reinterpret_cast<float2*>(&g_gi[(size_t)r0*G3 + gbase + colL]) = v0;
        *reinterpret_cast<float2*>(&g_gi[(size_t)(r0+8)*G3 + gbase + colL]) = v1;
      }
    }
  }
}

// ---------------------------------------------------------------------------
// K2: persistent GRU scan, env-pipelined phases.
// 128 CTAs x 384 threads, 2 envs per CTA.
// Phase A(t): matvec env0 step t (all warps)  ||  gates env1 step t-1 (warps 0-3)
// Phase B(t): matvec env1 step t (all warps)  ||  gates env0 step t   (warps 0-3)
// One __syncthreads per phase. gi/mask staged via smem, 2 phases ahead.
// ---------------------------------------------------------------------------
__device__ __forceinline__ void gate_math(
    int j, float m, const float* gi_b, const float* gh_b, float* h_b,
    float bgr, float bgz, float bgn,
    size_t out_idx, float* __restrict__ outs,
    float* __restrict__ h_final, size_t hf_idx, bool is_last)
{
  float gr = gi_b[j], gz = gi_b[128+j], gn = gi_b[256+j];
  float sr = gh_b[j], sz = gh_b[128+j], sn = gh_b[256+j];
  float hold = h_b[j];
  float r = sigf(gr + fmaf(m, sr, bgr));
  float z = sigf(gz + fmaf(m, sz, bgz));
  float n = tanhf_(gn + r * fmaf(m, sn, bgn));
  float hn = fmaf(z, fmaf(m, hold, -n), n);   // (1-z)*n + z*(m*hold)
  h_b[j] = hn;
  outs[out_idx] = hn;
  if (is_last && h_final != nullptr) h_final[hf_idx] = hn;
}

__global__ void __launch_bounds__(384, 1) k2_scan(
    const float* __restrict__ h0,
    const float* __restrict__ masks,
    const float* __restrict__ w_hh,
    const float* __restrict__ b_hh,
    float* __restrict__ outs,
    float* __restrict__ h_final)
{
  __shared__ __align__(16) float h_sm[2][HID];
  __shared__ float gh_sm[2][G3];
  __shared__ float gi_sm[2][G3];
  __shared__ float m_sm[2];

  const int g  = threadIdx.x;          // 0..383 == gate row
  const int j  = g & 127;
  const int e0 = blockIdx.x * 2;

  // weights: row g of w_hh, packed f32x2 (128 regs)
  unsigned long long wq[64];
  {
    const float4* wr = reinterpret_cast<const float4*>(w_hh + (size_t)g * HID);
    #pragma unroll
    for (int i = 0; i < 32; i++){
      float4 v = wr[i];
      wq[2*i]   = pk2(v.x, v.y);
      wq[2*i+1] = pk2(v.z, v.w);
    }
  }
  // gate-side biases (rows j, j+128, j+256)
  const float bgr = b_hh[j];
  const float bgz = b_hh[128 + j];
  const float bgn = b_hh[256 + j];

  if (g < 256) h_sm[g>>7][j] = h0[(size_t)(e0 + (g>>7))*HID + j];

  // running pointers
  const float* gp = g_gi + (size_t)e0*G3 + g;      // gi(t=0, env0, row g)
  const size_t STRIDE = (size_t)N_ENV*G3;
  // preload for A(0) staging: gi(0, env0), m(0, env0)
  float gi_reg = gp[0];
  float m_reg  = (g == 383) ? masks[e0] : 0.f;
  __syncthreads();

  size_t out_base0 = (size_t)e0*HID + j;           // env0, t=0
  const size_t OUT_STRIDE = (size_t)N_ENV*HID;

  #pragma unroll 1
  for (int t = 0; t < T_STEPS; t++){
    // ================= Phase A: matvec env0 | gates env1 (step t-1) ========
    gi_sm[0][g] = gi_reg;
    if (g == 383) m_sm[0] = m_reg;
    // prefetch for B(t) staging: gi(t, env1)
    gi_reg = gp[(size_t)t*STRIDE + G3];
    if (g == 383) m_reg = masks[(size_t)t*N_ENV + e0 + 1];

    if (g < 128 && t > 0){
      gate_math(j, m_sm[1], gi_sm[1], gh_sm[1], h_sm[1],
                bgr, bgz, bgn,
                (size_t)(t-1)*OUT_STRIDE + (size_t)(e0+1)*HID + j, outs,
                h_final, (size_t)(e0+1)*HID + j, false);
    }
    {
      const ulonglong2* hp = reinterpret_cast<const ulonglong2*>(h_sm[0]);
      unsigned long long A0=0, A1=0, A2=0, A3=0;
      #pragma unroll
      for (int i = 0; i < 16; i++){
        ulonglong2 v0 = hp[2*i];
        fma2(A0, wq[4*i],   v0.x);
        fma2(A1, wq[4*i+1], v0.y);
        ulonglong2 v1 = hp[2*i+1];
        fma2(A2, wq[4*i+2], v1.x);
        fma2(A3, wq[4*i+3], v1.y);
      }
      float2 f0=upk(A0), f1=upk(A1), f2=upk(A2), f3=upk(A3);
      gh_sm[0][g] = ((f0.x+f0.y)+(f1.x+f1.y)) + ((f2.x+f2.y)+(f3.x+f3.y));
    }
    __syncthreads();

    // ================= Phase B: matvec env1 | gates env0 (step t) ==========
    gi_sm[1][g] = gi_reg;
    if (g == 383) m_sm[1] = m_reg;
    // prefetch for A(t+1) staging: gi(t+1, env0)
    if (t + 1 < T_STEPS){
      gi_reg = gp[(size_t)(t+1)*STRIDE];
      if (g == 383) m_reg = masks[(size_t)(t+1)*N_ENV + e0];
    }

    if (g < 128){
      gate_math(j, m_sm[0], gi_sm[0], gh_sm[0], h_sm[0],
                bgr, bgz, bgn,
                (size_t)t*OUT_STRIDE + out_base0, outs,
                h_final, out_base0, t == T_STEPS-1);
    }
    {
      const ulonglong2* hp = reinterpret_cast<const ulonglong2*>(h_sm[1]);
      unsigned long long A0=0, A1=0, A2=0, A3=0;
      #pragma unroll
      for (int i = 0; i < 16; i++){
        ulonglong2 v0 = hp[2*i];
        fma2(A0, wq[4*i],   v0.x);
        fma2(A1, wq[4*i+1], v0.y);
        ulonglong2 v1 = hp[2*i+1];
        fma2(A2, wq[4*i+2], v1.x);
        fma2(A3, wq[4*i+3], v1.y);
      }
      float2 f0=upk(A0), f1=upk(A1), f2=upk(A2), f3=upk(A3);
      gh_sm[1][g] = ((f0.x+f0.y)+(f1.x+f1.y)) + ((f2.x+f2.y)+(f3.x+f3.y));
    }
    __syncthreads();
  }

  // ================= Epilogue: gates env1, step T-1 ========================
  if (g < 128){
    gate_math(j, m_sm[1], gi_sm[1], gh_sm[1], h_sm[1],
              bgr, bgz, bgn,
              (size_t)(T_STEPS-1)*OUT_STRIDE + (size_t)(e0+1)*HID + j, outs,
              h_final, (size_t)(e0+1)*HID + j, true);
  }
}

// ---------------------------------------------------------------------------
extern "C" void kernel_launch(void* const* d_in, const int* in_sizes, int n_in,
                              void* d_out, int out_size){
  (void)in_sizes; (void)n_in;
  const float* x     = (const float*)d_in[0];
  const float* h0    = (const float*)d_in[1];
  const float* masks = (const float*)d_in[2];
  const float* w_ih  = (const float*)d_in[3];
  const float* w_hh  = (const float*)d_in[4];
  const float* b_ih  = (const float*)d_in[5];
  const float* b_hh  = (const float*)d_in[6];

  float* outs = (float*)d_out;
  float* hf = nullptr;
  if ((long long)out_size >= (long long)M_TOTAL*HID + (long long)N_ENV*HID)
    hf = outs + (size_t)M_TOTAL*HID;

  const int k1_smem = (3*128*LDA + 128) * (int)sizeof(float);
  cudaFuncSetAttribute(k1_gi, cudaFuncAttributeMaxDynamicSharedMemorySize, k1_smem);
  k1_gi<<<dim3(3,128), 256, k1_smem>>>(x, w_ih, b_ih);
  k2_scan<<<128, 384>>>(h0, masks, w_hh, b_hh, outs, hf);
}